// round 1
// baseline (speedup 1.0000x reference)
#include <cuda_runtime.h>
#include <cuda_bf16.h>
#include <math_constants.h>

#define B_SAMPLES 32768
#define D_DIM 256
#define C_CLASSES 2048
#define EPSV 1e-12f

// ---------------- scratch (device globals; no allocation) ----------------
__device__ float g_f[B_SAMPLES * D_DIM];       // normalized features (32 MB)
__device__ float g_sums[C_CLASSES * D_DIM];    // per-class sums (2 MB)
__device__ float g_counts[C_CLASSES];
__device__ float g_cent[C_CLASSES * D_DIM];    // centroids (2 MB)
__device__ float g_pen[C_CLASSES];             // cn2 if count>0 else +inf
__device__ float g_s[B_SAMPLES];               // max_c (2*dot - cn2), masked
__device__ float g_acc[2];                     // {loss_sum, valid_cnt}

// ---------------- K0: zero scratch ----------------
__global__ void k_zero() {
    int i = blockIdx.x * blockDim.x + threadIdx.x;
    if (i < C_CLASSES * D_DIM) g_sums[i] = 0.0f;
    if (i < C_CLASSES) g_counts[i] = 0.0f;
    if (i < 2) g_acc[i] = 0.0f;
}

// ---------------- K1: normalize rows + segment-sum atomics ----------------
// one warp per sample row
__global__ void k_normalize(const float* __restrict__ feats,
                            const int* __restrict__ labels) {
    int warp = (blockIdx.x * blockDim.x + threadIdx.x) >> 5;
    int lane = threadIdx.x & 31;
    if (warp >= B_SAMPLES) return;

    const float4* frow = (const float4*)(feats + (size_t)warp * D_DIM);
    float4 v0 = frow[lane];        // dims lane*4 .. +3
    float4 v1 = frow[lane + 32];   // dims 128 + lane*4 .. +3

    float ss = v0.x*v0.x + v0.y*v0.y + v0.z*v0.z + v0.w*v0.w
             + v1.x*v1.x + v1.y*v1.y + v1.z*v1.z + v1.w*v1.w;
    #pragma unroll
    for (int off = 16; off >= 1; off >>= 1)
        ss += __shfl_xor_sync(0xffffffffu, ss, off);

    float inv = 1.0f / fmaxf(sqrtf(ss), EPSV);
    v0.x *= inv; v0.y *= inv; v0.z *= inv; v0.w *= inv;
    v1.x *= inv; v1.y *= inv; v1.z *= inv; v1.w *= inv;

    float4* orow = (float4*)(g_f + (size_t)warp * D_DIM);
    orow[lane] = v0;
    orow[lane + 32] = v1;

    int lab = labels[warp];
    float* srow = g_sums + (size_t)lab * D_DIM;
    int d0 = lane * 4;
    atomicAdd(&srow[d0 + 0], v0.x);
    atomicAdd(&srow[d0 + 1], v0.y);
    atomicAdd(&srow[d0 + 2], v0.z);
    atomicAdd(&srow[d0 + 3], v0.w);
    atomicAdd(&srow[128 + d0 + 0], v1.x);
    atomicAdd(&srow[128 + d0 + 1], v1.y);
    atomicAdd(&srow[128 + d0 + 2], v1.z);
    atomicAdd(&srow[128 + d0 + 3], v1.w);
    if (lane == 0) atomicAdd(&g_counts[lab], 1.0f);
}

// ---------------- K2: centroids + penalty (cn2 or +inf) ----------------
// one warp per class
__global__ void k_centroids() {
    int warp = (blockIdx.x * blockDim.x + threadIdx.x) >> 5;
    int lane = threadIdx.x & 31;
    if (warp >= C_CLASSES) return;

    float cnt = g_counts[warp];
    float inv = 1.0f / fmaxf(cnt, 1.0f);

    const float4* srow = (const float4*)(g_sums + (size_t)warp * D_DIM);
    float4 s0 = srow[lane];
    float4 s1 = srow[lane + 32];
    float4 c0 = make_float4(s0.x*inv, s0.y*inv, s0.z*inv, s0.w*inv);
    float4 c1 = make_float4(s1.x*inv, s1.y*inv, s1.z*inv, s1.w*inv);
    float4* crow = (float4*)(g_cent + (size_t)warp * D_DIM);
    crow[lane] = c0;
    crow[lane + 32] = c1;

    float ss = c0.x*c0.x + c0.y*c0.y + c0.z*c0.z + c0.w*c0.w
             + c1.x*c1.x + c1.y*c1.y + c1.z*c1.z + c1.w*c1.w;
    #pragma unroll
    for (int off = 16; off >= 1; off >>= 1)
        ss += __shfl_xor_sync(0xffffffffu, ss, off);

    if (lane == 0)
        g_pen[warp] = (cnt > 0.0f) ? ss : CUDART_INF_F;
}

// ---------------- K3: tiled GEMM with fused masked running-max ----------------
// For each sample i: g_s[i] = max over {c : count[c]>0, c != label[i]} of
//                    (2 * f_i . cent_c - cn2[c])
#define BM 128
#define BN 128
#define BK 16
#define SMP 136   // padded row stride (floats), 16B-aligned, conflict-free stores

__global__ __launch_bounds__(256, 2)
void k_gemm_max(const int* __restrict__ labels) {
    __shared__ float As[BK][SMP];
    __shared__ float Bs[BK][SMP];
    __shared__ int   labs[BM];

    int tid = threadIdx.x;
    int tx = tid & 15;        // column group (8 cols)
    int ty = tid >> 4;        // row group (8 rows)
    int row0 = blockIdx.x * BM;

    if (tid < BM) labs[tid] = labels[row0 + tid];

    float rowmax[8];
    #pragma unroll
    for (int r = 0; r < 8; r++) rowmax[r] = -CUDART_INF_F;

    for (int nb = 0; nb < C_CLASSES / BN; nb++) {
        int col0 = nb * BN;

        float acc[8][8];
        #pragma unroll
        for (int r = 0; r < 8; r++)
            #pragma unroll
            for (int c = 0; c < 8; c++) acc[r][c] = 0.0f;

        for (int kb = 0; kb < D_DIM / BK; kb++) {
            // stage A tile (transposed): As[k][m] = f[row0+m][kb*16+k]
            #pragma unroll
            for (int i = 0; i < 2; i++) {
                int l = tid + i * 256;         // 0..511
                int m = l >> 2;                // 0..127
                int kq = (l & 3) * 4;          // 0,4,8,12
                float4 v = *(const float4*)(g_f + (size_t)(row0 + m) * D_DIM + kb * BK + kq);
                As[kq + 0][m] = v.x;
                As[kq + 1][m] = v.y;
                As[kq + 2][m] = v.z;
                As[kq + 3][m] = v.w;
            }
            // stage B tile (transposed): Bs[k][n] = cent[col0+n][kb*16+k]
            #pragma unroll
            for (int i = 0; i < 2; i++) {
                int l = tid + i * 256;
                int n = l >> 2;
                int kq = (l & 3) * 4;
                float4 v = *(const float4*)(g_cent + (size_t)(col0 + n) * D_DIM + kb * BK + kq);
                Bs[kq + 0][n] = v.x;
                Bs[kq + 1][n] = v.y;
                Bs[kq + 2][n] = v.z;
                Bs[kq + 3][n] = v.w;
            }
            __syncthreads();

            #pragma unroll
            for (int k = 0; k < BK; k++) {
                float a[8], b[8];
                *(float4*)&a[0] = *(const float4*)&As[k][ty * 8];
                *(float4*)&a[4] = *(const float4*)&As[k][ty * 8 + 4];
                *(float4*)&b[0] = *(const float4*)&Bs[k][tx * 8];
                *(float4*)&b[4] = *(const float4*)&Bs[k][tx * 8 + 4];
                #pragma unroll
                for (int r = 0; r < 8; r++)
                    #pragma unroll
                    for (int c = 0; c < 8; c++)
                        acc[r][c] = fmaf(a[r], b[c], acc[r][c]);
            }
            __syncthreads();
        }

        // epilogue: fold this class chunk into per-row running max
        float pen_r[8];
        #pragma unroll
        for (int c = 0; c < 8; c++)
            pen_r[c] = g_pen[col0 + tx * 8 + c];

        #pragma unroll
        for (int r = 0; r < 8; r++) {
            int lab = labs[ty * 8 + r];
            #pragma unroll
            for (int c = 0; c < 8; c++) {
                int cc = col0 + tx * 8 + c;
                float sc = 2.0f * acc[r][c] - pen_r[c];   // -inf for empty classes
                if (cc != lab) rowmax[r] = fmaxf(rowmax[r], sc);
            }
        }
    }

    // reduce rowmax across the 16 tx-threads sharing each row (within warp halves)
    #pragma unroll
    for (int off = 8; off >= 1; off >>= 1) {
        #pragma unroll
        for (int r = 0; r < 8; r++)
            rowmax[r] = fmaxf(rowmax[r], __shfl_xor_sync(0xffffffffu, rowmax[r], off));
    }
    if (tx == 0) {
        #pragma unroll
        for (int r = 0; r < 8; r++)
            g_s[row0 + ty * 8 + r] = rowmax[r];
    }
}

// ---------------- K4: d_p + per-sample loss + reduction ----------------
__device__ __forceinline__ float softplus_stable(float x) {
    return (x > 0.0f) ? (x + log1pf(expf(-x))) : log1pf(expf(x));
}

__global__ void k_loss(const int* __restrict__ labels,
                       const int* __restrict__ epoch_p) {
    __shared__ float s_loss, s_cnt;
    if (threadIdx.x == 0) { s_loss = 0.0f; s_cnt = 0.0f; }
    __syncthreads();

    int sample = blockIdx.x * 8 + (threadIdx.x >> 5);
    int lane = threadIdx.x & 31;

    if (sample < B_SAMPLES) {
        int lab = labels[sample];
        float cnt = g_counts[lab];
        float m = fmaxf(cnt - 1.0f, 1.0f);
        float invm = 1.0f / m;

        const float4* fr = (const float4*)(g_f + (size_t)sample * D_DIM);
        const float4* sr = (const float4*)(g_sums + (size_t)lab * D_DIM);
        float acc = 0.0f;
        #pragma unroll
        for (int i = 0; i < 2; i++) {
            float4 fv = fr[lane + i * 32];
            float4 sv = sr[lane + i * 32];
            float t;
            t = fv.x - (sv.x - fv.x) * invm; acc += t * t;
            t = fv.y - (sv.y - fv.y) * invm; acc += t * t;
            t = fv.z - (sv.z - fv.z) * invm; acc += t * t;
            t = fv.w - (sv.w - fv.w) * invm; acc += t * t;
        }
        #pragma unroll
        for (int off = 16; off >= 1; off >>= 1)
            acc += __shfl_xor_sync(0xffffffffu, acc, off);

        if (lane == 0) {
            float s = g_s[sample];
            bool valid = (cnt > 1.0f) && (s > -1e37f);
            if (valid) {
                float dp = sqrtf(acc + EPSV);
                float dn = sqrtf(fmaxf(1.0f - s, EPSV));
                // decode epoch defensively (int32 expected; tolerate float bits)
                int iv = epoch_p[0];
                float ev = (iv >= 0 && iv < 100000) ? (float)iv : __int_as_float(iv);
                float temp = fminf(0.3f + 0.02f * ev, 1.0f);
                float x = (dp - dn) / temp;
                atomicAdd(&s_loss, softplus_stable(x));
                atomicAdd(&s_cnt, 1.0f);
            }
        }
    }
    __syncthreads();
    if (threadIdx.x == 0) {
        atomicAdd(&g_acc[0], s_loss);
        atomicAdd(&g_acc[1], s_cnt);
    }
}

// ---------------- K5: finalize ----------------
__global__ void k_final(float* __restrict__ out) {
    float sum = g_acc[0];
    float c = g_acc[1];
    out[0] = (c > 0.0f) ? (sum / fmaxf(c, 1.0f)) : 0.0f;  // WEIGHT = 1.0
}

// ---------------- launch ----------------
extern "C" void kernel_launch(void* const* d_in, const int* in_sizes, int n_in,
                              void* d_out, int out_size) {
    const float* feats = (const float*)d_in[0];
    const int* labels = (const int*)d_in[1];
    const int* epoch = (const int*)d_in[2];
    float* out = (float*)d_out;

    // K0: zero scratch
    {
        int n = C_CLASSES * D_DIM;
        k_zero<<<(n + 255) / 256, 256>>>();
    }
    // K1: normalize + segment sums (one warp/row)
    k_normalize<<<(B_SAMPLES * 32) / 256, 256>>>(feats, labels);
    // K2: centroids + penalties (one warp/class)
    k_centroids<<<(C_CLASSES * 32) / 256, 256>>>();
    // K3: GEMM + masked max
    k_gemm_max<<<B_SAMPLES / BM, 256>>>(labels);
    // K4: d_p + loss accumulation
    k_loss<<<B_SAMPLES / 8, 256>>>(labels, epoch);
    // K5: finalize
    k_final<<<1, 1>>>(out);
}

// round 3
// speedup vs baseline: 3.9534x; 3.9534x over previous
#include <cuda_runtime.h>
#include <cuda_bf16.h>
#include <math_constants.h>
#include <cstdint>

#define B_SAMPLES 32768
#define D_DIM 256
#define C_CLASSES 2048
#define NTILES 16              // C / 128
#define EPSV 1e-12f

// ---------------- scratch (device globals; no allocation) ----------------
__device__ __nv_bfloat16 g_A[B_SAMPLES * D_DIM];   // normalized feats, bf16 (16 MB)
__device__ __nv_bfloat16 g_B[C_CLASSES * D_DIM];   // centroids, bf16 (1 MB)
__device__ float g_sums[C_CLASSES * D_DIM];        // fp32 class sums (2 MB)
__device__ float g_counts[C_CLASSES];
__device__ float g_pen[C_CLASSES];                 // cn2 if count>0 else +inf
__device__ float g_smax[NTILES * B_SAMPLES];       // per-Ntile partial max of (2*dot - cn2)
__device__ float g_acc[2];                         // {loss_sum, valid_cnt}

// ---------------- helpers ----------------
__device__ __forceinline__ uint32_t smem_u32(const void* p) {
    uint32_t a;
    asm("{ .reg .u64 t; cvta.to.shared.u64 t, %1; cvt.u32.u64 %0, t; }" : "=r"(a) : "l"(p));
    return a;
}
__device__ __forceinline__ void cp16(uint32_t dst, const void* src) {
    asm volatile("cp.async.cg.shared.global [%0], [%1], 16;" :: "r"(dst), "l"(src) : "memory");
}
__device__ __forceinline__ void ldsm_x4(uint32_t& r0, uint32_t& r1, uint32_t& r2, uint32_t& r3,
                                        uint32_t addr) {
    asm volatile("ldmatrix.sync.aligned.m8n8.x4.shared.b16 {%0,%1,%2,%3}, [%4];"
                 : "=r"(r0), "=r"(r1), "=r"(r2), "=r"(r3) : "r"(addr));
}
__device__ __forceinline__ void mma_bf16(float* d, const uint32_t* a, uint32_t b0, uint32_t b1) {
    asm volatile(
        "mma.sync.aligned.m16n8k16.row.col.f32.bf16.bf16.f32 "
        "{%0,%1,%2,%3}, {%4,%5,%6,%7}, {%8,%9}, {%0,%1,%2,%3};"
        : "+f"(d[0]), "+f"(d[1]), "+f"(d[2]), "+f"(d[3])
        : "r"(a[0]), "r"(a[1]), "r"(a[2]), "r"(a[3]), "r"(b0), "r"(b1));
}
__device__ __forceinline__ uint32_t pack_bf16(float x, float y) {
    __nv_bfloat162 h = __floats2bfloat162_rn(x, y);
    return *(uint32_t*)&h;
}

// ---------------- K0: zero scratch ----------------
__global__ void k_zero() {
    int i = blockIdx.x * blockDim.x + threadIdx.x;
    if (i < C_CLASSES * D_DIM) g_sums[i] = 0.0f;
    if (i < C_CLASSES) g_counts[i] = 0.0f;
    if (i < 2) g_acc[i] = 0.0f;
}

// ---------------- K1: normalize + bf16 store + segment sums ----------------
__global__ void k_normalize(const float* __restrict__ feats,
                            const int* __restrict__ labels) {
    int warp = (blockIdx.x * blockDim.x + threadIdx.x) >> 5;
    int lane = threadIdx.x & 31;
    if (warp >= B_SAMPLES) return;

    const float4* frow = (const float4*)(feats + (size_t)warp * D_DIM);
    float4 v0 = frow[lane];
    float4 v1 = frow[lane + 32];

    float ss = v0.x*v0.x + v0.y*v0.y + v0.z*v0.z + v0.w*v0.w
             + v1.x*v1.x + v1.y*v1.y + v1.z*v1.z + v1.w*v1.w;
    #pragma unroll
    for (int off = 16; off >= 1; off >>= 1) ss += __shfl_xor_sync(0xffffffffu, ss, off);

    float inv = 1.0f / fmaxf(sqrtf(ss), EPSV);
    v0.x *= inv; v0.y *= inv; v0.z *= inv; v0.w *= inv;
    v1.x *= inv; v1.y *= inv; v1.z *= inv; v1.w *= inv;

    __nv_bfloat16* ar = g_A + (size_t)warp * D_DIM;
    int d0 = lane * 4;
    uint2 p0 = make_uint2(pack_bf16(v0.x, v0.y), pack_bf16(v0.z, v0.w));
    uint2 p1 = make_uint2(pack_bf16(v1.x, v1.y), pack_bf16(v1.z, v1.w));
    *(uint2*)(ar + d0) = p0;
    *(uint2*)(ar + 128 + d0) = p1;

    int lab = labels[warp];
    float* srow = g_sums + (size_t)lab * D_DIM;
    atomicAdd(&srow[d0 + 0], v0.x);
    atomicAdd(&srow[d0 + 1], v0.y);
    atomicAdd(&srow[d0 + 2], v0.z);
    atomicAdd(&srow[d0 + 3], v0.w);
    atomicAdd(&srow[128 + d0 + 0], v1.x);
    atomicAdd(&srow[128 + d0 + 1], v1.y);
    atomicAdd(&srow[128 + d0 + 2], v1.z);
    atomicAdd(&srow[128 + d0 + 3], v1.w);
    if (lane == 0) atomicAdd(&g_counts[lab], 1.0f);
}

// ---------------- K2: centroids -> bf16 + penalty ----------------
__global__ void k_centroids() {
    int warp = (blockIdx.x * blockDim.x + threadIdx.x) >> 5;
    int lane = threadIdx.x & 31;
    if (warp >= C_CLASSES) return;

    float cnt = g_counts[warp];
    float inv = 1.0f / fmaxf(cnt, 1.0f);

    const float4* srow = (const float4*)(g_sums + (size_t)warp * D_DIM);
    float4 s0 = srow[lane];
    float4 s1 = srow[lane + 32];
    float4 c0 = make_float4(s0.x*inv, s0.y*inv, s0.z*inv, s0.w*inv);
    float4 c1 = make_float4(s1.x*inv, s1.y*inv, s1.z*inv, s1.w*inv);

    __nv_bfloat16* br = g_B + (size_t)warp * D_DIM;
    int d0 = lane * 4;
    *(uint2*)(br + d0) = make_uint2(pack_bf16(c0.x, c0.y), pack_bf16(c0.z, c0.w));
    *(uint2*)(br + 128 + d0) = make_uint2(pack_bf16(c1.x, c1.y), pack_bf16(c1.z, c1.w));

    float ss = c0.x*c0.x + c0.y*c0.y + c0.z*c0.z + c0.w*c0.w
             + c1.x*c1.x + c1.y*c1.y + c1.z*c1.z + c1.w*c1.w;
    #pragma unroll
    for (int off = 16; off >= 1; off >>= 1) ss += __shfl_xor_sync(0xffffffffu, ss, off);

    if (lane == 0) g_pen[warp] = (cnt > 0.0f) ? ss : CUDART_INF_F;
}

// ---------------- K3: mma.sync bf16 GEMM + fused masked max ----------------
// CTA: 128(M) x 128(N) x K=256, BK=32 double-buffered cp.async.
// 8 warps, warp tile 32(M) x 64(N). grid = (B/128, C/128).
#define SSTRIDE 40   // bf16 elements per smem row (80 bytes): conflict-free ldmatrix

__global__ __launch_bounds__(256, 2)
void k_gemm_mma(const int* __restrict__ labels) {
    __shared__ __align__(16) __nv_bfloat16 As[2][128 * SSTRIDE];
    __shared__ __align__(16) __nv_bfloat16 Bs[2][128 * SSTRIDE];
    __shared__ float s_pen[128];
    __shared__ int   s_lab[128];
    __shared__ float s_row[128];

    int tid = threadIdx.x;
    int wid = tid >> 5;
    int lane = tid & 31;
    int arow0 = blockIdx.x * 128;
    int brow0 = blockIdx.y * 128;

    if (tid < 128) {
        s_pen[tid] = g_pen[brow0 + tid];
        s_lab[tid] = labels[arow0 + tid];
    }

    uint32_t asb[2] = { smem_u32(&As[0][0]), smem_u32(&As[1][0]) };
    uint32_t bsb[2] = { smem_u32(&Bs[0][0]), smem_u32(&Bs[1][0]) };

    float acc[2][8][4];
    #pragma unroll
    for (int mt = 0; mt < 2; mt++)
        #pragma unroll
        for (int n8 = 0; n8 < 8; n8++)
            #pragma unroll
            for (int e = 0; e < 4; e++) acc[mt][n8][e] = 0.0f;

    // ldmatrix lane address offsets
    int lr = lane & 15;
    int koff = (lane >> 4) * 8;
    uint32_t aoff = (uint32_t)(((wid & 3) * 32 + lr) * SSTRIDE + koff) * 2;
    uint32_t boff = (uint32_t)(((wid >> 2) * 64 + lr) * SSTRIDE + koff) * 2;

    auto stage = [&](int kb, int buf) {
        #pragma unroll
        for (int i = 0; i < 2; i++) {
            int l = tid + i * 256;
            int r = l >> 2, c = l & 3;
            uint32_t so = (uint32_t)(r * SSTRIDE * 2 + c * 16);
            cp16(asb[buf] + so, g_A + (size_t)(arow0 + r) * D_DIM + kb * 32 + c * 8);
            cp16(bsb[buf] + so, g_B + (size_t)(brow0 + r) * D_DIM + kb * 32 + c * 8);
        }
        asm volatile("cp.async.commit_group;" ::: "memory");
    };

    stage(0, 0);

    for (int kb = 0; kb < 8; kb++) {
        int buf = kb & 1;
        if (kb + 1 < 8) {
            stage(kb + 1, buf ^ 1);
            asm volatile("cp.async.wait_group 1;" ::: "memory");
        } else {
            asm volatile("cp.async.wait_group 0;" ::: "memory");
        }
        __syncthreads();

        #pragma unroll
        for (int ks = 0; ks < 2; ks++) {
            uint32_t a[2][4], b[4][4];
            #pragma unroll
            for (int mt = 0; mt < 2; mt++)
                ldsm_x4(a[mt][0], a[mt][1], a[mt][2], a[mt][3],
                        asb[buf] + aoff + (uint32_t)(mt * 16 * SSTRIDE * 2 + ks * 32));
            #pragma unroll
            for (int nt = 0; nt < 4; nt++)
                ldsm_x4(b[nt][0], b[nt][1], b[nt][2], b[nt][3],
                        bsb[buf] + boff + (uint32_t)(nt * 16 * SSTRIDE * 2 + ks * 32));
            #pragma unroll
            for (int mt = 0; mt < 2; mt++)
                #pragma unroll
                for (int n8 = 0; n8 < 8; n8++) {
                    int nt = n8 >> 1, o = n8 & 1;
                    mma_bf16(acc[mt][n8], a[mt], b[nt][o], b[nt][o + 2]);
                }
        }
        __syncthreads();
    }

    // epilogue: masked max over this CTA's 128 classes
    int r4 = lane >> 2;
    int c2 = lane & 3;
    float rmax[4];
    #pragma unroll
    for (int mt = 0; mt < 2; mt++) {
        #pragma unroll
        for (int h = 0; h < 2; h++) {
            int m_local = (wid & 3) * 32 + mt * 16 + h * 8 + r4;
            int lab = s_lab[m_local];
            float mx = -CUDART_INF_F;
            #pragma unroll
            for (int n8 = 0; n8 < 8; n8++) {
                int n_local = (wid >> 2) * 64 + n8 * 8 + c2 * 2;
                int cls0 = brow0 + n_local;
                float sc0 = 2.0f * acc[mt][n8][h * 2 + 0] - s_pen[n_local];
                float sc1 = 2.0f * acc[mt][n8][h * 2 + 1] - s_pen[n_local + 1];
                if (cls0 != lab)     mx = fmaxf(mx, sc0);
                if (cls0 + 1 != lab) mx = fmaxf(mx, sc1);
            }
            rmax[mt * 2 + h] = mx;
        }
    }
    // reduce over the 4 threads (lane&3) sharing each row
    #pragma unroll
    for (int off = 1; off <= 2; off <<= 1)
        #pragma unroll
        for (int i = 0; i < 4; i++)
            rmax[i] = fmaxf(rmax[i], __shfl_xor_sync(0xffffffffu, rmax[i], off));

    if (wid < 4) {
        if (c2 == 0) {
            #pragma unroll
            for (int i = 0; i < 4; i++) {
                int m_local = (wid & 3) * 32 + (i >> 1) * 16 + (i & 1) * 8 + r4;
                s_row[m_local] = rmax[i];
            }
        }
    }
    __syncthreads();
    if (wid >= 4 && c2 == 0) {
        #pragma unroll
        for (int i = 0; i < 4; i++) {
            int m_local = (wid & 3) * 32 + (i >> 1) * 16 + (i & 1) * 8 + r4;
            g_smax[(size_t)blockIdx.y * B_SAMPLES + arow0 + m_local] =
                fmaxf(rmax[i], s_row[m_local]);
        }
    }
}

// ---------------- K4: d_p + loss + reduction ----------------
__device__ __forceinline__ float softplus_stable(float x) {
    return (x > 0.0f) ? (x + log1pf(expf(-x))) : log1pf(expf(x));
}

__global__ void k_loss(const float* __restrict__ feats,
                       const int* __restrict__ labels,
                       const int* __restrict__ epoch_p) {
    __shared__ float s_loss, s_cnt;
    if (threadIdx.x == 0) { s_loss = 0.0f; s_cnt = 0.0f; }
    __syncthreads();

    int sample = blockIdx.x * 8 + (threadIdx.x >> 5);
    int lane = threadIdx.x & 31;

    if (sample < B_SAMPLES) {
        // renormalize from raw features (exact fp32)
        const float4* fr = (const float4*)(feats + (size_t)sample * D_DIM);
        float4 v0 = fr[lane];
        float4 v1 = fr[lane + 32];
        float ss = v0.x*v0.x + v0.y*v0.y + v0.z*v0.z + v0.w*v0.w
                 + v1.x*v1.x + v1.y*v1.y + v1.z*v1.z + v1.w*v1.w;
        #pragma unroll
        for (int off = 16; off >= 1; off >>= 1) ss += __shfl_xor_sync(0xffffffffu, ss, off);
        float inv = 1.0f / fmaxf(sqrtf(ss), EPSV);
        v0.x *= inv; v0.y *= inv; v0.z *= inv; v0.w *= inv;
        v1.x *= inv; v1.y *= inv; v1.z *= inv; v1.w *= inv;

        int lab = labels[sample];
        float cnt = g_counts[lab];
        float m = fmaxf(cnt - 1.0f, 1.0f);
        float invm = 1.0f / m;

        const float4* sr = (const float4*)(g_sums + (size_t)lab * D_DIM);
        float4 sv0 = sr[lane];
        float4 sv1 = sr[lane + 32];
        float accd = 0.0f, t;
        t = v0.x - (sv0.x - v0.x) * invm; accd += t * t;
        t = v0.y - (sv0.y - v0.y) * invm; accd += t * t;
        t = v0.z - (sv0.z - v0.z) * invm; accd += t * t;
        t = v0.w - (sv0.w - v0.w) * invm; accd += t * t;
        t = v1.x - (sv1.x - v1.x) * invm; accd += t * t;
        t = v1.y - (sv1.y - v1.y) * invm; accd += t * t;
        t = v1.z - (sv1.z - v1.z) * invm; accd += t * t;
        t = v1.w - (sv1.w - v1.w) * invm; accd += t * t;
        #pragma unroll
        for (int off = 16; off >= 1; off >>= 1)
            accd += __shfl_xor_sync(0xffffffffu, accd, off);

        if (lane == 0) {
            float s = -CUDART_INF_F;
            #pragma unroll
            for (int p = 0; p < NTILES; p++)
                s = fmaxf(s, g_smax[(size_t)p * B_SAMPLES + sample]);
            bool valid = (cnt > 1.0f) && (s > -1e37f);
            if (valid) {
                float dp = sqrtf(accd + EPSV);
                float dn = sqrtf(fmaxf(1.0f - s, EPSV));
                int iv = epoch_p[0];
                float ev = (iv >= 0 && iv < 100000) ? (float)iv : __int_as_float(iv);
                float temp = fminf(0.3f + 0.02f * ev, 1.0f);
                float x = (dp - dn) / temp;
                atomicAdd(&s_loss, softplus_stable(x));
                atomicAdd(&s_cnt, 1.0f);
            }
        }
    }
    __syncthreads();
    if (threadIdx.x == 0) {
        atomicAdd(&g_acc[0], s_loss);
        atomicAdd(&g_acc[1], s_cnt);
    }
}

// ---------------- K5: finalize ----------------
__global__ void k_final(float* __restrict__ out) {
    float sum = g_acc[0];
    float c = g_acc[1];
    out[0] = (c > 0.0f) ? (sum / fmaxf(c, 1.0f)) : 0.0f;
}

// ---------------- launch ----------------
extern "C" void kernel_launch(void* const* d_in, const int* in_sizes, int n_in,
                              void* d_out, int out_size) {
    const float* feats = (const float*)d_in[0];
    const int* labels = (const int*)d_in[1];
    const int* epoch = (const int*)d_in[2];
    float* out = (float*)d_out;

    {
        int n = C_CLASSES * D_DIM;
        k_zero<<<(n + 255) / 256, 256>>>();
    }
    k_normalize<<<(B_SAMPLES * 32) / 256, 256>>>(feats, labels);
    k_centroids<<<(C_CLASSES * 32) / 256, 256>>>();
    k_gemm_mma<<<dim3(B_SAMPLES / 128, C_CLASSES / 128), 256>>>(labels);
    k_loss<<<B_SAMPLES / 8, 256>>>(feats, labels, epoch);
    k_final<<<1, 1>>>(out);
}

// round 4
// speedup vs baseline: 5.9005x; 1.4925x over previous
#include <cuda_runtime.h>
#include <cuda_bf16.h>
#include <math_constants.h>
#include <cstdint>

#define B_SAMPLES 32768
#define D_DIM 256
#define C_CLASSES 2048
#define NTILES 16              // C / 128
#define EPSV 1e-12f

// ---------------- scratch (device globals; no allocation) ----------------
__device__ __nv_bfloat16 g_A[B_SAMPLES * D_DIM];   // normalized feats, bf16 (16 MB)
__device__ __nv_bfloat16 g_B[C_CLASSES * D_DIM];   // centroids, bf16 (1 MB)
__device__ float g_sums[C_CLASSES * D_DIM];        // fp32 class sums (2 MB)
__device__ float g_counts[C_CLASSES];
__device__ float g_pen[C_CLASSES];                 // cn2 if count>0 else +inf
__device__ float g_smax[NTILES * B_SAMPLES];       // per-Ntile partial max of (2*dot - cn2)
__device__ float g_acc[2];                         // {loss_sum, valid_cnt}

// ---------------- helpers ----------------
__device__ __forceinline__ uint32_t smem_u32(const void* p) {
    uint32_t a;
    asm("{ .reg .u64 t; cvta.to.shared.u64 t, %1; cvt.u32.u64 %0, t; }" : "=r"(a) : "l"(p));
    return a;
}
__device__ __forceinline__ void cp16(uint32_t dst, const void* src) {
    asm volatile("cp.async.cg.shared.global [%0], [%1], 16;" :: "r"(dst), "l"(src) : "memory");
}
template <int N>
__device__ __forceinline__ void cp_wait() {
    asm volatile("cp.async.wait_group %0;" :: "n"(N) : "memory");
}
__device__ __forceinline__ void cp_commit() {
    asm volatile("cp.async.commit_group;" ::: "memory");
}
__device__ __forceinline__ void ldsm_x4(uint32_t& r0, uint32_t& r1, uint32_t& r2, uint32_t& r3,
                                        uint32_t addr) {
    asm volatile("ldmatrix.sync.aligned.m8n8.x4.shared.b16 {%0,%1,%2,%3}, [%4];"
                 : "=r"(r0), "=r"(r1), "=r"(r2), "=r"(r3) : "r"(addr));
}
__device__ __forceinline__ void mma_bf16(float* d, const uint32_t* a, uint32_t b0, uint32_t b1) {
    asm volatile(
        "mma.sync.aligned.m16n8k16.row.col.f32.bf16.bf16.f32 "
        "{%0,%1,%2,%3}, {%4,%5,%6,%7}, {%8,%9}, {%0,%1,%2,%3};"
        : "+f"(d[0]), "+f"(d[1]), "+f"(d[2]), "+f"(d[3])
        : "r"(a[0]), "r"(a[1]), "r"(a[2]), "r"(a[3]), "r"(b0), "r"(b1));
}
__device__ __forceinline__ uint32_t pack_bf16(float x, float y) {
    __nv_bfloat162 h = __floats2bfloat162_rn(x, y);
    return *(uint32_t*)&h;
}

// ---------------- K0: zero scratch ----------------
__global__ void k_zero() {
    int i = blockIdx.x * blockDim.x + threadIdx.x;
    if (i < C_CLASSES * D_DIM) g_sums[i] = 0.0f;
    if (i < C_CLASSES) g_counts[i] = 0.0f;
    if (i < 2) g_acc[i] = 0.0f;
}

// ---------------- K1: normalize + bf16 store + segment sums ----------------
__global__ void k_normalize(const float* __restrict__ feats,
                            const int* __restrict__ labels) {
    int warp = (blockIdx.x * blockDim.x + threadIdx.x) >> 5;
    int lane = threadIdx.x & 31;
    if (warp >= B_SAMPLES) return;

    const float4* frow = (const float4*)(feats + (size_t)warp * D_DIM);
    float4 v0 = frow[lane];
    float4 v1 = frow[lane + 32];

    float ss = v0.x*v0.x + v0.y*v0.y + v0.z*v0.z + v0.w*v0.w
             + v1.x*v1.x + v1.y*v1.y + v1.z*v1.z + v1.w*v1.w;
    #pragma unroll
    for (int off = 16; off >= 1; off >>= 1) ss += __shfl_xor_sync(0xffffffffu, ss, off);

    float inv = 1.0f / fmaxf(sqrtf(ss), EPSV);
    v0.x *= inv; v0.y *= inv; v0.z *= inv; v0.w *= inv;
    v1.x *= inv; v1.y *= inv; v1.z *= inv; v1.w *= inv;

    __nv_bfloat16* ar = g_A + (size_t)warp * D_DIM;
    int d0 = lane * 4;
    *(uint2*)(ar + d0) = make_uint2(pack_bf16(v0.x, v0.y), pack_bf16(v0.z, v0.w));
    *(uint2*)(ar + 128 + d0) = make_uint2(pack_bf16(v1.x, v1.y), pack_bf16(v1.z, v1.w));

    int lab = labels[warp];
    float* srow = g_sums + (size_t)lab * D_DIM;
    atomicAdd(&srow[d0 + 0], v0.x);
    atomicAdd(&srow[d0 + 1], v0.y);
    atomicAdd(&srow[d0 + 2], v0.z);
    atomicAdd(&srow[d0 + 3], v0.w);
    atomicAdd(&srow[128 + d0 + 0], v1.x);
    atomicAdd(&srow[128 + d0 + 1], v1.y);
    atomicAdd(&srow[128 + d0 + 2], v1.z);
    atomicAdd(&srow[128 + d0 + 3], v1.w);
    if (lane == 0) atomicAdd(&g_counts[lab], 1.0f);
}

// ---------------- K2: centroids -> bf16 + penalty ----------------
__global__ void k_centroids() {
    int warp = (blockIdx.x * blockDim.x + threadIdx.x) >> 5;
    int lane = threadIdx.x & 31;
    if (warp >= C_CLASSES) return;

    float cnt = g_counts[warp];
    float inv = 1.0f / fmaxf(cnt, 1.0f);

    const float4* srow = (const float4*)(g_sums + (size_t)warp * D_DIM);
    float4 s0 = srow[lane];
    float4 s1 = srow[lane + 32];
    float4 c0 = make_float4(s0.x*inv, s0.y*inv, s0.z*inv, s0.w*inv);
    float4 c1 = make_float4(s1.x*inv, s1.y*inv, s1.z*inv, s1.w*inv);

    __nv_bfloat16* br = g_B + (size_t)warp * D_DIM;
    int d0 = lane * 4;
    *(uint2*)(br + d0) = make_uint2(pack_bf16(c0.x, c0.y), pack_bf16(c0.z, c0.w));
    *(uint2*)(br + 128 + d0) = make_uint2(pack_bf16(c1.x, c1.y), pack_bf16(c1.z, c1.w));

    float ss = c0.x*c0.x + c0.y*c0.y + c0.z*c0.z + c0.w*c0.w
             + c1.x*c1.x + c1.y*c1.y + c1.z*c1.z + c1.w*c1.w;
    #pragma unroll
    for (int off = 16; off >= 1; off >>= 1) ss += __shfl_xor_sync(0xffffffffu, ss, off);

    if (lane == 0) g_pen[warp] = (cnt > 0.0f) ? ss : CUDART_INF_F;
}

// ---------------- K3: mma.sync bf16 GEMM + fused masked max ----------------
// CTA: 128(M) x 128(N), K=256 in 8 chunks of 32, 4-stage cp.async pipeline,
// one __syncthreads per chunk. 8 warps, warp tile 32(M) x 64(N).
#define SSTRIDE 40                      // bf16 elems per smem row (80 B)
#define TILE_BYTES (128 * SSTRIDE * 2)  // 10240 B per (A or B) stage
#define STAGE_BYTES (2 * TILE_BYTES)    // 20480 B
#define NSTAGES 4
#define DSMEM_TOTAL (NSTAGES * STAGE_BYTES)  // 81920 B

__global__ __launch_bounds__(256, 2)
void k_gemm_mma(const int* __restrict__ labels) {
    extern __shared__ __align__(16) char dsm[];
    __shared__ float s_pen[128];
    __shared__ int   s_lab[128];
    __shared__ float s_row[128];

    int tid = threadIdx.x;
    int wid = tid >> 5;
    int lane = tid & 31;
    int arow0 = blockIdx.x * 128;
    int brow0 = blockIdx.y * 128;

    if (tid < 128) {
        s_pen[tid] = g_pen[brow0 + tid];
        s_lab[tid] = labels[arow0 + tid];
    }

    uint32_t sb = smem_u32(dsm);
    uint32_t a_s[NSTAGES], b_s[NSTAGES];
    #pragma unroll
    for (int s = 0; s < NSTAGES; s++) {
        a_s[s] = sb + s * STAGE_BYTES;
        b_s[s] = a_s[s] + TILE_BYTES;
    }

    // per-thread staging pointers (2 rows of A and 2 of B per thread per chunk)
    const __nv_bfloat16* gA0 = g_A + (size_t)(arow0 + (tid >> 2)) * D_DIM + (tid & 3) * 8;
    const __nv_bfloat16* gA1 = gA0 + (size_t)64 * D_DIM;
    const __nv_bfloat16* gB0 = g_B + (size_t)(brow0 + (tid >> 2)) * D_DIM + (tid & 3) * 8;
    const __nv_bfloat16* gB1 = gB0 + (size_t)64 * D_DIM;
    uint32_t so0 = (uint32_t)((tid >> 2) * SSTRIDE * 2 + (tid & 3) * 16);
    uint32_t so1 = so0 + 64 * SSTRIDE * 2;

    auto stage = [&](int kb, int s) {
        cp16(a_s[s] + so0, gA0 + kb * 32);
        cp16(a_s[s] + so1, gA1 + kb * 32);
        cp16(b_s[s] + so0, gB0 + kb * 32);
        cp16(b_s[s] + so1, gB1 + kb * 32);
        cp_commit();
    };

    float acc[2][8][4];
    #pragma unroll
    for (int mt = 0; mt < 2; mt++)
        #pragma unroll
        for (int n8 = 0; n8 < 8; n8++)
            #pragma unroll
            for (int e = 0; e < 4; e++) acc[mt][n8][e] = 0.0f;

    // ldmatrix lane offsets (relative to stage base)
    int lr = lane & 15;
    int koff = (lane >> 4) * 8;
    uint32_t aoff = (uint32_t)(((wid & 3) * 32 + lr) * SSTRIDE + koff) * 2;
    uint32_t boff = (uint32_t)(((wid >> 2) * 64 + lr) * SSTRIDE + koff) * 2;

    stage(0, 0);
    stage(1, 1);
    stage(2, 2);

    #pragma unroll
    for (int kb = 0; kb < 8; kb++) {
        const int s = kb & 3;
        // groups staged by top of iter kb: up to min(kb+2, 7); need group kb done
        if (kb <= 5)      cp_wait<2>();
        else if (kb == 6) cp_wait<1>();
        else              cp_wait<0>();
        __syncthreads();   // slot s data visible; all warps done with slot (kb+3)&3
        if (kb + 3 < 8) stage(kb + 3, (kb + 3) & 3);

        #pragma unroll
        for (int ks = 0; ks < 2; ks++) {
            uint32_t a[2][4], b[4][4];
            #pragma unroll
            for (int mt = 0; mt < 2; mt++)
                ldsm_x4(a[mt][0], a[mt][1], a[mt][2], a[mt][3],
                        a_s[s] + aoff + (uint32_t)(mt * 16 * SSTRIDE * 2 + ks * 32));
            #pragma unroll
            for (int nt = 0; nt < 4; nt++)
                ldsm_x4(b[nt][0], b[nt][1], b[nt][2], b[nt][3],
                        b_s[s] + boff + (uint32_t)(nt * 16 * SSTRIDE * 2 + ks * 32));
            #pragma unroll
            for (int mt = 0; mt < 2; mt++)
                #pragma unroll
                for (int n8 = 0; n8 < 8; n8++) {
                    int nt = n8 >> 1, o = n8 & 1;
                    mma_bf16(acc[mt][n8], a[mt], b[nt][o], b[nt][o + 2]);
                }
        }
    }

    // epilogue: masked max over this CTA's 128 classes
    int r4 = lane >> 2;
    int c2 = lane & 3;
    float rmax[4];
    #pragma unroll
    for (int mt = 0; mt < 2; mt++) {
        #pragma unroll
        for (int h = 0; h < 2; h++) {
            int m_local = (wid & 3) * 32 + mt * 16 + h * 8 + r4;
            int lab = s_lab[m_local];
            float mx = -CUDART_INF_F;
            #pragma unroll
            for (int n8 = 0; n8 < 8; n8++) {
                int n_local = (wid >> 2) * 64 + n8 * 8 + c2 * 2;
                int cls0 = brow0 + n_local;
                float sc0 = 2.0f * acc[mt][n8][h * 2 + 0] - s_pen[n_local];
                float sc1 = 2.0f * acc[mt][n8][h * 2 + 1] - s_pen[n_local + 1];
                if (cls0 != lab)     mx = fmaxf(mx, sc0);
                if (cls0 + 1 != lab) mx = fmaxf(mx, sc1);
            }
            rmax[mt * 2 + h] = mx;
        }
    }
    #pragma unroll
    for (int off = 1; off <= 2; off <<= 1)
        #pragma unroll
        for (int i = 0; i < 4; i++)
            rmax[i] = fmaxf(rmax[i], __shfl_xor_sync(0xffffffffu, rmax[i], off));

    if (wid < 4 && c2 == 0) {
        #pragma unroll
        for (int i = 0; i < 4; i++) {
            int m_local = (wid & 3) * 32 + (i >> 1) * 16 + (i & 1) * 8 + r4;
            s_row[m_local] = rmax[i];
        }
    }
    __syncthreads();
    if (wid >= 4 && c2 == 0) {
        #pragma unroll
        for (int i = 0; i < 4; i++) {
            int m_local = (wid & 3) * 32 + (i >> 1) * 16 + (i & 1) * 8 + r4;
            g_smax[(size_t)blockIdx.y * B_SAMPLES + arow0 + m_local] =
                fmaxf(rmax[i], s_row[m_local]);
        }
    }
}

// ---------------- K4: d_p + loss + reduction ----------------
__device__ __forceinline__ float softplus_stable(float x) {
    return (x > 0.0f) ? (x + log1pf(expf(-x))) : log1pf(expf(x));
}

__global__ void k_loss(const float* __restrict__ feats,
                       const int* __restrict__ labels,
                       const int* __restrict__ epoch_p) {
    __shared__ float s_loss, s_cnt;
    if (threadIdx.x == 0) { s_loss = 0.0f; s_cnt = 0.0f; }
    __syncthreads();

    int sample = blockIdx.x * 8 + (threadIdx.x >> 5);
    int lane = threadIdx.x & 31;

    if (sample < B_SAMPLES) {
        const float4* fr = (const float4*)(feats + (size_t)sample * D_DIM);
        float4 v0 = fr[lane];
        float4 v1 = fr[lane + 32];
        float ss = v0.x*v0.x + v0.y*v0.y + v0.z*v0.z + v0.w*v0.w
                 + v1.x*v1.x + v1.y*v1.y + v1.z*v1.z + v1.w*v1.w;
        #pragma unroll
        for (int off = 16; off >= 1; off >>= 1) ss += __shfl_xor_sync(0xffffffffu, ss, off);
        float inv = 1.0f / fmaxf(sqrtf(ss), EPSV);
        v0.x *= inv; v0.y *= inv; v0.z *= inv; v0.w *= inv;
        v1.x *= inv; v1.y *= inv; v1.z *= inv; v1.w *= inv;

        int lab = labels[sample];
        float cnt = g_counts[lab];
        float m = fmaxf(cnt - 1.0f, 1.0f);
        float invm = 1.0f / m;

        const float4* sr = (const float4*)(g_sums + (size_t)lab * D_DIM);
        float4 sv0 = sr[lane];
        float4 sv1 = sr[lane + 32];
        float accd = 0.0f, t;
        t = v0.x - (sv0.x - v0.x) * invm; accd += t * t;
        t = v0.y - (sv0.y - v0.y) * invm; accd += t * t;
        t = v0.z - (sv0.z - v0.z) * invm; accd += t * t;
        t = v0.w - (sv0.w - v0.w) * invm; accd += t * t;
        t = v1.x - (sv1.x - v1.x) * invm; accd += t * t;
        t = v1.y - (sv1.y - v1.y) * invm; accd += t * t;
        t = v1.z - (sv1.z - v1.z) * invm; accd += t * t;
        t = v1.w - (sv1.w - v1.w) * invm; accd += t * t;
        #pragma unroll
        for (int off = 16; off >= 1; off >>= 1)
            accd += __shfl_xor_sync(0xffffffffu, accd, off);

        if (lane == 0) {
            float s = -CUDART_INF_F;
            #pragma unroll
            for (int p = 0; p < NTILES; p++)
                s = fmaxf(s, g_smax[(size_t)p * B_SAMPLES + sample]);
            bool valid = (cnt > 1.0f) && (s > -1e37f);
            if (valid) {
                float dp = sqrtf(accd + EPSV);
                float dn = sqrtf(fmaxf(1.0f - s, EPSV));
                int iv = epoch_p[0];
                float ev = (iv >= 0 && iv < 100000) ? (float)iv : __int_as_float(iv);
                float temp = fminf(0.3f + 0.02f * ev, 1.0f);
                float x = (dp - dn) / temp;
                atomicAdd(&s_loss, softplus_stable(x));
                atomicAdd(&s_cnt, 1.0f);
            }
        }
    }
    __syncthreads();
    if (threadIdx.x == 0) {
        atomicAdd(&g_acc[0], s_loss);
        atomicAdd(&g_acc[1], s_cnt);
    }
}

// ---------------- K5: finalize ----------------
__global__ void k_final(float* __restrict__ out) {
    float sum = g_acc[0];
    float c = g_acc[1];
    out[0] = (c > 0.0f) ? (sum / fmaxf(c, 1.0f)) : 0.0f;
}

// ---------------- launch ----------------
extern "C" void kernel_launch(void* const* d_in, const int* in_sizes, int n_in,
                              void* d_out, int out_size) {
    const float* feats = (const float*)d_in[0];
    const int* labels = (const int*)d_in[1];
    const int* epoch = (const int*)d_in[2];
    float* out = (float*)d_out;

    static int configured = 0;
    if (!configured) {
        cudaFuncSetAttribute(k_gemm_mma, cudaFuncAttributeMaxDynamicSharedMemorySize,
                             DSMEM_TOTAL);
        configured = 1;
    }

    {
        int n = C_CLASSES * D_DIM;
        k_zero<<<(n + 255) / 256, 256>>>();
    }
    k_normalize<<<(B_SAMPLES * 32) / 256, 256>>>(feats, labels);
    k_centroids<<<(C_CLASSES * 32) / 256, 256>>>();
    k_gemm_mma<<<dim3(B_SAMPLES / 128, C_CLASSES / 128), 256, DSMEM_TOTAL>>>(labels);
    k_loss<<<B_SAMPLES / 8, 256>>>(feats, labels, epoch);
    k_final<<<1, 1>>>(out);
}

// round 5
// speedup vs baseline: 6.3404x; 1.0745x over previous
#include <cuda_runtime.h>
#include <cuda_bf16.h>
#include <math_constants.h>
#include <cstdint>

#define B_SAMPLES 32768
#define D_DIM 256
#define C_CLASSES 2048
#define NTILES 16              // C / 128
#define EPSV 1e-12f

// ---------------- scratch (device globals; no allocation) ----------------
__device__ __nv_bfloat16 g_A[B_SAMPLES * D_DIM];   // normalized feats, bf16 (16 MB)
__device__ __nv_bfloat16 g_B[C_CLASSES * D_DIM];   // centroids, bf16 (1 MB)
__device__ float g_sums[C_CLASSES * D_DIM];        // fp32 class sums (2 MB)
__device__ float g_counts[C_CLASSES];
__device__ float g_pen[C_CLASSES];                 // cn2 if count>0 else +inf
__device__ float g_smax[NTILES * B_SAMPLES];       // per-Ntile partial max of (2*dot - cn2)
__device__ float g_own[B_SAMPLES];                 // f_i . centroid[label_i]
__device__ float g_acc[2];                         // {loss_sum, valid_cnt}
__device__ unsigned int g_done;

// ---------------- helpers ----------------
__device__ __forceinline__ uint32_t smem_u32(const void* p) {
    uint32_t a;
    asm("{ .reg .u64 t; cvta.to.shared.u64 t, %1; cvt.u32.u64 %0, t; }" : "=r"(a) : "l"(p));
    return a;
}
__device__ __forceinline__ void cp16(uint32_t dst, const void* src) {
    asm volatile("cp.async.cg.shared.global [%0], [%1], 16;" :: "r"(dst), "l"(src) : "memory");
}
template <int N>
__device__ __forceinline__ void cp_wait() {
    asm volatile("cp.async.wait_group %0;" :: "n"(N) : "memory");
}
__device__ __forceinline__ void cp_commit() {
    asm volatile("cp.async.commit_group;" ::: "memory");
}
__device__ __forceinline__ void ldsm_x4(uint32_t& r0, uint32_t& r1, uint32_t& r2, uint32_t& r3,
                                        uint32_t addr) {
    asm volatile("ldmatrix.sync.aligned.m8n8.x4.shared.b16 {%0,%1,%2,%3}, [%4];"
                 : "=r"(r0), "=r"(r1), "=r"(r2), "=r"(r3) : "r"(addr));
}
__device__ __forceinline__ void mma_bf16(float* d, const uint32_t* a, uint32_t b0, uint32_t b1) {
    asm volatile(
        "mma.sync.aligned.m16n8k16.row.col.f32.bf16.bf16.f32 "
        "{%0,%1,%2,%3}, {%4,%5,%6,%7}, {%8,%9}, {%0,%1,%2,%3};"
        : "+f"(d[0]), "+f"(d[1]), "+f"(d[2]), "+f"(d[3])
        : "r"(a[0]), "r"(a[1]), "r"(a[2]), "r"(a[3]), "r"(b0), "r"(b1));
}
__device__ __forceinline__ uint32_t pack_bf16(float x, float y) {
    __nv_bfloat162 h = __floats2bfloat162_rn(x, y);
    return *(uint32_t*)&h;
}

// ---------------- K0: zero scratch ----------------
__global__ void k_zero() {
    int i = blockIdx.x * blockDim.x + threadIdx.x;
    if (i < C_CLASSES * D_DIM) g_sums[i] = 0.0f;
    if (i < C_CLASSES) g_counts[i] = 0.0f;
    if (i < 2) g_acc[i] = 0.0f;
    if (i == 2) g_done = 0u;
}

// ---------------- K1: normalize + bf16 store + segment sums ----------------
__global__ void k_normalize(const float* __restrict__ feats,
                            const int* __restrict__ labels) {
    int warp = (blockIdx.x * blockDim.x + threadIdx.x) >> 5;
    int lane = threadIdx.x & 31;
    if (warp >= B_SAMPLES) return;

    const float4* frow = (const float4*)(feats + (size_t)warp * D_DIM);
    float4 v0 = frow[lane];
    float4 v1 = frow[lane + 32];

    float ss = v0.x*v0.x + v0.y*v0.y + v0.z*v0.z + v0.w*v0.w
             + v1.x*v1.x + v1.y*v1.y + v1.z*v1.z + v1.w*v1.w;
    #pragma unroll
    for (int off = 16; off >= 1; off >>= 1) ss += __shfl_xor_sync(0xffffffffu, ss, off);

    float inv = 1.0f / fmaxf(sqrtf(ss), EPSV);
    v0.x *= inv; v0.y *= inv; v0.z *= inv; v0.w *= inv;
    v1.x *= inv; v1.y *= inv; v1.z *= inv; v1.w *= inv;

    __nv_bfloat16* ar = g_A + (size_t)warp * D_DIM;
    int d0 = lane * 4;
    *(uint2*)(ar + d0) = make_uint2(pack_bf16(v0.x, v0.y), pack_bf16(v0.z, v0.w));
    *(uint2*)(ar + 128 + d0) = make_uint2(pack_bf16(v1.x, v1.y), pack_bf16(v1.z, v1.w));

    int lab = labels[warp];
    float* srow = g_sums + (size_t)lab * D_DIM;
    atomicAdd(&srow[d0 + 0], v0.x);
    atomicAdd(&srow[d0 + 1], v0.y);
    atomicAdd(&srow[d0 + 2], v0.z);
    atomicAdd(&srow[d0 + 3], v0.w);
    atomicAdd(&srow[128 + d0 + 0], v1.x);
    atomicAdd(&srow[128 + d0 + 1], v1.y);
    atomicAdd(&srow[128 + d0 + 2], v1.z);
    atomicAdd(&srow[128 + d0 + 3], v1.w);
    if (lane == 0) atomicAdd(&g_counts[lab], 1.0f);
}

// ---------------- K2: centroids -> bf16 + penalty ----------------
__global__ void k_centroids() {
    int warp = (blockIdx.x * blockDim.x + threadIdx.x) >> 5;
    int lane = threadIdx.x & 31;
    if (warp >= C_CLASSES) return;

    float cnt = g_counts[warp];
    float inv = 1.0f / fmaxf(cnt, 1.0f);

    const float4* srow = (const float4*)(g_sums + (size_t)warp * D_DIM);
    float4 s0 = srow[lane];
    float4 s1 = srow[lane + 32];
    float4 c0 = make_float4(s0.x*inv, s0.y*inv, s0.z*inv, s0.w*inv);
    float4 c1 = make_float4(s1.x*inv, s1.y*inv, s1.z*inv, s1.w*inv);

    __nv_bfloat16* br = g_B + (size_t)warp * D_DIM;
    int d0 = lane * 4;
    *(uint2*)(br + d0) = make_uint2(pack_bf16(c0.x, c0.y), pack_bf16(c0.z, c0.w));
    *(uint2*)(br + 128 + d0) = make_uint2(pack_bf16(c1.x, c1.y), pack_bf16(c1.z, c1.w));

    float ss = c0.x*c0.x + c0.y*c0.y + c0.z*c0.z + c0.w*c0.w
             + c1.x*c1.x + c1.y*c1.y + c1.z*c1.z + c1.w*c1.w;
    #pragma unroll
    for (int off = 16; off >= 1; off >>= 1) ss += __shfl_xor_sync(0xffffffffu, ss, off);

    if (lane == 0) g_pen[warp] = (cnt > 0.0f) ? ss : CUDART_INF_F;
}

// ---------------- K3: mma.sync bf16 GEMM + fused masked max + own-dot ----------------
#define SSTRIDE 40                      // bf16 elems per smem row (80 B)
#define TILE_BYTES (128 * SSTRIDE * 2)  // 10240 B per (A or B) stage
#define STAGE_BYTES (2 * TILE_BYTES)    // 20480 B
#define NSTAGES 4
#define DSMEM_TOTAL (NSTAGES * STAGE_BYTES)  // 81920 B

__global__ __launch_bounds__(256, 2)
void k_gemm_mma(const int* __restrict__ labels) {
    extern __shared__ __align__(16) char dsm[];
    __shared__ float s_pen[128];
    __shared__ int   s_lab[128];
    __shared__ float s_row[128];

    int tid = threadIdx.x;
    int wid = tid >> 5;
    int lane = tid & 31;
    int arow0 = blockIdx.x * 128;
    int brow0 = blockIdx.y * 128;

    if (tid < 128) {
        s_pen[tid] = g_pen[brow0 + tid];
        s_lab[tid] = labels[arow0 + tid];
    }

    uint32_t sb = smem_u32(dsm);
    uint32_t a_s[NSTAGES], b_s[NSTAGES];
    #pragma unroll
    for (int s = 0; s < NSTAGES; s++) {
        a_s[s] = sb + s * STAGE_BYTES;
        b_s[s] = a_s[s] + TILE_BYTES;
    }

    const __nv_bfloat16* gA0 = g_A + (size_t)(arow0 + (tid >> 2)) * D_DIM + (tid & 3) * 8;
    const __nv_bfloat16* gA1 = gA0 + (size_t)64 * D_DIM;
    const __nv_bfloat16* gB0 = g_B + (size_t)(brow0 + (tid >> 2)) * D_DIM + (tid & 3) * 8;
    const __nv_bfloat16* gB1 = gB0 + (size_t)64 * D_DIM;
    uint32_t so0 = (uint32_t)((tid >> 2) * SSTRIDE * 2 + (tid & 3) * 16);
    uint32_t so1 = so0 + 64 * SSTRIDE * 2;

    auto stage = [&](int kb, int s) {
        cp16(a_s[s] + so0, gA0 + kb * 32);
        cp16(a_s[s] + so1, gA1 + kb * 32);
        cp16(b_s[s] + so0, gB0 + kb * 32);
        cp16(b_s[s] + so1, gB1 + kb * 32);
        cp_commit();
    };

    float acc[2][8][4];
    #pragma unroll
    for (int mt = 0; mt < 2; mt++)
        #pragma unroll
        for (int n8 = 0; n8 < 8; n8++)
            #pragma unroll
            for (int e = 0; e < 4; e++) acc[mt][n8][e] = 0.0f;

    int lr = lane & 15;
    int koff = (lane >> 4) * 8;
    uint32_t aoff = (uint32_t)(((wid & 3) * 32 + lr) * SSTRIDE + koff) * 2;
    uint32_t boff = (uint32_t)(((wid >> 2) * 64 + lr) * SSTRIDE + koff) * 2;

    stage(0, 0);
    stage(1, 1);
    stage(2, 2);

    #pragma unroll
    for (int kb = 0; kb < 8; kb++) {
        const int s = kb & 3;
        if (kb <= 5)      cp_wait<2>();
        else if (kb == 6) cp_wait<1>();
        else              cp_wait<0>();
        __syncthreads();
        if (kb + 3 < 8) stage(kb + 3, (kb + 3) & 3);

        // issue ALL fragment loads for both ks-steps first (long HMMA run after)
        uint32_t a0[2][4], a1[2][4], b0[4][4], b1[4][4];
        #pragma unroll
        for (int mt = 0; mt < 2; mt++) {
            uint32_t base = a_s[s] + aoff + (uint32_t)(mt * 16 * SSTRIDE * 2);
            ldsm_x4(a0[mt][0], a0[mt][1], a0[mt][2], a0[mt][3], base);
            ldsm_x4(a1[mt][0], a1[mt][1], a1[mt][2], a1[mt][3], base + 32);
        }
        #pragma unroll
        for (int nt = 0; nt < 4; nt++) {
            uint32_t base = b_s[s] + boff + (uint32_t)(nt * 16 * SSTRIDE * 2);
            ldsm_x4(b0[nt][0], b0[nt][1], b0[nt][2], b0[nt][3], base);
            ldsm_x4(b1[nt][0], b1[nt][1], b1[nt][2], b1[nt][3], base + 32);
        }
        #pragma unroll
        for (int mt = 0; mt < 2; mt++)
            #pragma unroll
            for (int n8 = 0; n8 < 8; n8++) {
                int nt = n8 >> 1, o = n8 & 1;
                mma_bf16(acc[mt][n8], a0[mt], b0[nt][o], b0[nt][o + 2]);
            }
        #pragma unroll
        for (int mt = 0; mt < 2; mt++)
            #pragma unroll
            for (int n8 = 0; n8 < 8; n8++) {
                int nt = n8 >> 1, o = n8 & 1;
                mma_bf16(acc[mt][n8], a1[mt], b1[nt][o], b1[nt][o + 2]);
            }
    }

    // epilogue: masked max over this CTA's 128 classes + own-class dot export
    int r4 = lane >> 2;
    int c2 = lane & 3;
    float rmax[4];
    #pragma unroll
    for (int mt = 0; mt < 2; mt++) {
        #pragma unroll
        for (int h = 0; h < 2; h++) {
            int m_local = (wid & 3) * 32 + mt * 16 + h * 8 + r4;
            int lab = s_lab[m_local];
            float mx = -CUDART_INF_F;
            #pragma unroll
            for (int n8 = 0; n8 < 8; n8++) {
                int n_local = (wid >> 2) * 64 + n8 * 8 + c2 * 2;
                int cls0 = brow0 + n_local;
                float d0v = acc[mt][n8][h * 2 + 0];
                float d1v = acc[mt][n8][h * 2 + 1];
                float sc0 = 2.0f * d0v - s_pen[n_local];
                float sc1 = 2.0f * d1v - s_pen[n_local + 1];
                if (cls0 != lab)     mx = fmaxf(mx, sc0);
                else                 g_own[arow0 + m_local] = d0v;
                if (cls0 + 1 != lab) mx = fmaxf(mx, sc1);
                else                 g_own[arow0 + m_local] = d1v;
            }
            rmax[mt * 2 + h] = mx;
        }
    }
    #pragma unroll
    for (int off = 1; off <= 2; off <<= 1)
        #pragma unroll
        for (int i = 0; i < 4; i++)
            rmax[i] = fmaxf(rmax[i], __shfl_xor_sync(0xffffffffu, rmax[i], off));

    if (wid < 4 && c2 == 0) {
        #pragma unroll
        for (int i = 0; i < 4; i++) {
            int m_local = (wid & 3) * 32 + (i >> 1) * 16 + (i & 1) * 8 + r4;
            s_row[m_local] = rmax[i];
        }
    }
    __syncthreads();
    if (wid >= 4 && c2 == 0) {
        #pragma unroll
        for (int i = 0; i < 4; i++) {
            int m_local = (wid & 3) * 32 + (i >> 1) * 16 + (i & 1) * 8 + r4;
            g_smax[(size_t)blockIdx.y * B_SAMPLES + arow0 + m_local] =
                fmaxf(rmax[i], s_row[m_local]);
        }
    }
}

// ---------------- K4: scalar d_p + loss + full reduction + finalize ----------------
__device__ __forceinline__ float softplus_stable(float x) {
    return (x > 0.0f) ? (x + log1pf(expf(-x))) : log1pf(expf(x));
}

#define LOSS_BLOCKS (B_SAMPLES / 256)

__global__ void k_loss(const int* __restrict__ labels,
                       const int* __restrict__ epoch_p,
                       float* __restrict__ out) {
    __shared__ float s_part[2];
    int i = blockIdx.x * 256 + threadIdx.x;
    if (threadIdx.x == 0) { s_part[0] = 0.0f; s_part[1] = 0.0f; }
    __syncthreads();

    int lab = labels[i];
    float cnt = g_counts[lab];
    float s = -CUDART_INF_F;
    #pragma unroll
    for (int p = 0; p < NTILES; p++)
        s = fmaxf(s, g_smax[(size_t)p * B_SAMPLES + i]);

    float lv = 0.0f, cv = 0.0f;
    if ((cnt > 1.0f) && (s > -1e37f)) {
        float dotv = g_own[i];
        float cn2 = g_pen[lab];
        float m = cnt - 1.0f;                 // cnt > 1 here
        float invm = 1.0f / m;
        float fS = cnt * dotv;                 // f . S
        float S2 = cnt * cnt * cn2;            // ||S||^2
        float dp2 = 1.0f - 2.0f * (fS - 1.0f) * invm
                  + (S2 - 2.0f * fS + 1.0f) * invm * invm;
        float dp = sqrtf(fmaxf(dp2, 0.0f) + EPSV);
        float dn = sqrtf(fmaxf(1.0f - s, EPSV));
        int iv = epoch_p[0];
        float ev = (iv >= 0 && iv < 100000) ? (float)iv : __int_as_float(iv);
        float temp = fminf(0.3f + 0.02f * ev, 1.0f);
        lv = softplus_stable((dp - dn) / temp);
        cv = 1.0f;
    }
    // warp reduce then shared atomic
    #pragma unroll
    for (int off = 16; off >= 1; off >>= 1) {
        lv += __shfl_xor_sync(0xffffffffu, lv, off);
        cv += __shfl_xor_sync(0xffffffffu, cv, off);
    }
    if ((threadIdx.x & 31) == 0) {
        atomicAdd(&s_part[0], lv);
        atomicAdd(&s_part[1], cv);
    }
    __syncthreads();
    if (threadIdx.x == 0) {
        atomicAdd(&g_acc[0], s_part[0]);
        atomicAdd(&g_acc[1], s_part[1]);
        __threadfence();
        unsigned int done = atomicAdd(&g_done, 1u);
        if (done == LOSS_BLOCKS - 1) {
            float sum = g_acc[0];
            float c = g_acc[1];
            out[0] = (c > 0.0f) ? (sum / fmaxf(c, 1.0f)) : 0.0f;
        }
    }
}

// ---------------- launch ----------------
extern "C" void kernel_launch(void* const* d_in, const int* in_sizes, int n_in,
                              void* d_out, int out_size) {
    const float* feats = (const float*)d_in[0];
    const int* labels = (const int*)d_in[1];
    const int* epoch = (const int*)d_in[2];
    float* out = (float*)d_out;

    static int configured = 0;
    if (!configured) {
        cudaFuncSetAttribute(k_gemm_mma, cudaFuncAttributeMaxDynamicSharedMemorySize,
                             DSMEM_TOTAL);
        configured = 1;
    }

    {
        int n = C_CLASSES * D_DIM;
        k_zero<<<(n + 255) / 256, 256>>>();
    }
    k_normalize<<<(B_SAMPLES * 32) / 256, 256>>>(feats, labels);
    k_centroids<<<(C_CLASSES * 32) / 256, 256>>>();
    k_gemm_mma<<<dim3(B_SAMPLES / 128, C_CLASSES / 128), 256, DSMEM_TOTAL>>>(labels);
    k_loss<<<LOSS_BLOCKS, 256>>>(labels, epoch, out);
}